// round 5
// baseline (speedup 1.0000x reference)
#include <cuda_runtime.h>
#include <cstdint>

#define B_    32
#define IC_   16
#define OC_   16
#define KTOT  65536      // (M-1)*(N-1)
#define E_    131584     // edges
#define VOFF  65792      // M*(N-1)
#define KT    32         // k per tile (never crosses a 256-wide row)
#define NBUF  4          // weight pipeline depth

__device__ __forceinline__ unsigned long long pack2(float lo, float hi) {
    unsigned long long r;
    asm("mov.b64 %0, {%1, %2};" : "=l"(r) : "f"(lo), "f"(hi));
    return r;
}
__device__ __forceinline__ void fma2(unsigned long long &acc,
                                     unsigned long long a, unsigned long long b) {
    asm("fma.rn.f32x2 %0, %1, %2, %0;" : "+l"(acc) : "l"(a), "l"(b));
}
__device__ __forceinline__ float2 unpack2(unsigned long long v) {
    float2 f;
    asm("mov.b64 {%0, %1}, %2;" : "=f"(f.x), "=f"(f.y) : "l"(v));
    return f;
}
__device__ __forceinline__ void cp_async16(unsigned dst, const void* src) {
    asm volatile("cp.async.cg.shared.global [%0], [%1], 16;\n"
                 :: "r"(dst), "l"(src) : "memory");
}
__device__ __forceinline__ void cp_commit() {
    asm volatile("cp.async.commit_group;\n" ::: "memory");
}
template<int N>
__device__ __forceinline__ void cp_wait() {
    asm volatile("cp.async.wait_group %0;\n" :: "n"(N) : "memory");
}
__device__ __forceinline__ float ldg_off(const char* p, int byteoff) {
    float v;
    asm("ld.global.nc.f32 %0, [%1];" : "=f"(v) : "l"(p + byteoff));
    return v;
}

// Block: 32 k-lanes x 16 warps. y = oh*8 + bg.
// Block covers one 32-wide k tile, all 32 batches, all 16 o-channels
// => every weight element read from DRAM exactly once.
__global__ __launch_bounds__(512, 1)
void edges_kernel(const float* __restrict__ x,
                  const float4* __restrict__ w4,
                  const float* __restrict__ bias,
                  float* __restrict__ out)
{
    __shared__ float4 sw[NBUF][16 * KT];   // [buf][o*32 + klocal]

    const int lane = threadIdx.x;
    const int y    = threadIdx.y;
    const int oh   = y >> 3;
    const int bg   = y & 7;
    const int bbase = bg * 4;

    const int k0 = blockIdx.x * KT;
    const int k  = k0 + lane;
    const int i  = k0 >> 8;
    const int c0 = k;                                   // t0; t1 = c0+256
    const int c2 = VOFF + i * 257 + (k0 & 255) + lane;  // t2; t3 = c2+1

    // cooperative weight copy: 512 threads x 16B = 8 KB slab per ic
    const int tld = y * 32 + lane;
    const float4* wsrc = w4 + (size_t)((tld >> 5) * IC_) * KTOT + k0 + (tld & 31);
    const unsigned swdst0 = (unsigned)__cvta_generic_to_shared(&sw[0][tld]);

    // persistent x pointers: advance by E_*4 bytes per ic; loads use imm offsets
    const char* pA[4];   // -> x[b, ic, c0];       [p], [p+1024]
    const char* pB[4];   // -> x[b, ic, c2];       [p], [p+4]
    #pragma unroll
    for (int bb = 0; bb < 4; ++bb) {
        const float* xb = x + (size_t)((bbase + bb) * IC_) * E_;
        pA[bb] = (const char*)(xb + c0);
        pB[bb] = (const char*)(xb + c2);
    }

    unsigned long long acc[8][4];
    #pragma unroll
    for (int oo = 0; oo < 8; ++oo)
        #pragma unroll
        for (int bb = 0; bb < 4; ++bb) acc[oo][bb] = 0ull;

    // ---- prologue: weight stages 0..2 + x gather for ic=0 ----
    #pragma unroll
    for (int s = 0; s < 3; ++s) {
        cp_async16(swdst0 + s * (16 * KT * 16), wsrc + (size_t)s * KTOT);
        cp_commit();
    }

    float xf[4][4];
    #pragma unroll
    for (int bb = 0; bb < 4; ++bb) {
        xf[bb][0] = ldg_off(pA[bb], 0);
        xf[bb][1] = ldg_off(pA[bb], 1024);
        xf[bb][2] = ldg_off(pB[bb], 0);
        xf[bb][3] = ldg_off(pB[bb], 4);
        pA[bb] += E_ * 4;
        pB[bb] += E_ * 4;
    }

    #pragma unroll 4
    for (int ic = 0; ic < IC_; ++ic) {
        if (ic <= IC_ - 3)      cp_wait<2>();
        else if (ic == IC_ - 2) cp_wait<1>();
        else                    cp_wait<0>();
        __syncthreads();

        if (ic + 3 < IC_) {
            cp_async16(swdst0 + ((ic + 3) & (NBUF - 1)) * (16 * KT * 16),
                       wsrc + (size_t)(ic + 3) * KTOT);
            cp_commit();
        }

        // pack current x
        unsigned long long xA[4], xB[4];
        #pragma unroll
        for (int bb = 0; bb < 4; ++bb) {
            xA[bb] = pack2(xf[bb][0], xf[bb][1]);
            xB[bb] = pack2(xf[bb][2], xf[bb][3]);
        }

        // prefetch x for ic+1 (imm-offset LDGs, pointer bump)
        if (ic < IC_ - 1) {
            #pragma unroll
            for (int bb = 0; bb < 4; ++bb) {
                xf[bb][0] = ldg_off(pA[bb], 0);
                xf[bb][1] = ldg_off(pA[bb], 1024);
                xf[bb][2] = ldg_off(pB[bb], 0);
                xf[bb][3] = ldg_off(pB[bb], 4);
                pA[bb] += E_ * 4;
                pB[bb] += E_ * 4;
            }
        }

        // compute: 8 o x 4 b x 2 fma2
        const float4* swrow = &sw[ic & (NBUF - 1)][(oh * 8) * KT + lane];
        unsigned sa0 = (unsigned)__cvta_generic_to_shared(swrow);
        #pragma unroll
        for (int oo = 0; oo < 8; ++oo) {
            unsigned long long wA, wB;
            asm("ld.shared.v2.u64 {%0, %1}, [%2];"
                : "=l"(wA), "=l"(wB) : "r"(sa0 + oo * (KT * 16)));
            #pragma unroll
            for (int bb = 0; bb < 4; ++bb) {
                fma2(acc[oo][bb], wA, xA[bb]);
                fma2(acc[oo][bb], wB, xB[bb]);
            }
        }
    }

    // epilogue
    #pragma unroll
    for (int oo = 0; oo < 8; ++oo) {
        const int o = oh * 8 + oo;
        const float bo = __ldg(&bias[o]);
        #pragma unroll
        for (int bb = 0; bb < 4; ++bb) {
            float2 v = unpack2(acc[oo][bb]);
            out[(size_t)((bbase + bb) * OC_ + o) * KTOT + k] = v.x + v.y + bo;
        }
    }
}

extern "C" void kernel_launch(void* const* d_in, const int* in_sizes, int n_in,
                              void* d_out, int out_size)
{
    const float*  x    = (const float*)d_in[0];
    const float4* w4   = (const float4*)d_in[1];
    const float*  bias = (const float*)d_in[2];
    float*        out  = (float*)d_out;

    dim3 block(32, 16);
    dim3 grid(KTOT / KT);
    edges_kernel<<<grid, block>>>(x, w4, bias, out);
}

// round 6
// speedup vs baseline: 1.2517x; 1.2517x over previous
#include <cuda_runtime.h>
#include <cstdint>

#define B_    32
#define IC_   16
#define OC_   16
#define KTOT  65536      // (M-1)*(N-1)
#define E_    131584     // edges
#define VOFF  65792      // M*(N-1)
#define KT    32         // k per tile (never crosses a 256-wide row)
#define NBUF  4          // weight pipeline depth
#define SLAB  (8 * KT)   // float4s per ic slab (8 o-channels)

__device__ __forceinline__ unsigned long long pack2(float lo, float hi) {
    unsigned long long r;
    asm("mov.b64 %0, {%1, %2};" : "=l"(r) : "f"(lo), "f"(hi));
    return r;
}
__device__ __forceinline__ void fma2(unsigned long long &acc,
                                     unsigned long long a, unsigned long long b) {
    asm("fma.rn.f32x2 %0, %1, %2, %0;" : "+l"(acc) : "l"(a), "l"(b));
}
__device__ __forceinline__ float2 unpack2(unsigned long long v) {
    float2 f;
    asm("mov.b64 {%0, %1}, %2;" : "=f"(f.x), "=f"(f.y) : "l"(v));
    return f;
}
__device__ __forceinline__ void cp_async16(unsigned dst, const void* src) {
    asm volatile("cp.async.cg.shared.global [%0], [%1], 16;\n"
                 :: "r"(dst), "l"(src) : "memory");
}
__device__ __forceinline__ void cp_commit() {
    asm volatile("cp.async.commit_group;\n" ::: "memory");
}
template<int N>
__device__ __forceinline__ void cp_wait() {
    asm volatile("cp.async.wait_group %0;\n" :: "n"(N) : "memory");
}

// CTA: 32 k-lanes x 8 warps (bg). Each CTA owns HALF the o-channels (oh),
// all 32 batches, one 32-wide k tile. o-ranges are disjoint across CTAs
// => weights still stream from DRAM exactly once. Two CTAs per SM give two
// independent barrier/pipeline domains (mutual latency hiding).
__global__ __launch_bounds__(256, 2)
void edges_kernel(const float* __restrict__ x,
                  const float4* __restrict__ w4,
                  const float* __restrict__ bias,
                  float* __restrict__ out)
{
    __shared__ float4 sw[NBUF][SLAB];   // [buf][o*32 + klocal], o local 0..7

    const int lane = threadIdx.x;
    const int bg   = threadIdx.y;       // 0..7
    const int bbase = bg * 4;

    const int oh   = blockIdx.x & 1;
    const int tile = blockIdx.x >> 1;

    const int k0 = tile * KT;
    const int k  = k0 + lane;
    const int i  = k0 >> 8;
    const int c0 = k;                                   // t0; t1 = c0+256
    const int c2 = VOFF + i * 257 + (k0 & 255) + lane;  // t2; t3 = c2+1

    // cooperative weight copy: 256 threads x 16B = one 4 KB slab per ic
    // thread tld loads w4[(oh*8 + tld>>5)*IC*KTOT + ic*KTOT + k0 + (tld&31)]
    const int tld = bg * 32 + lane;
    const float4* wsrc = w4
        + (size_t)((oh * 8 + (tld >> 5)) * IC_) * KTOT + k0 + (tld & 31);
    const unsigned swdst0 = (unsigned)__cvta_generic_to_shared(&sw[0][tld]);

    const float* xp[4];
    #pragma unroll
    for (int bb = 0; bb < 4; ++bb)
        xp[bb] = x + (size_t)((bbase + bb) * IC_) * E_;

    unsigned long long acc[8][4];
    #pragma unroll
    for (int oo = 0; oo < 8; ++oo)
        #pragma unroll
        for (int bb = 0; bb < 4; ++bb) acc[oo][bb] = 0ull;

    // ---- prologue: weight stages 0..2 + x gather for ic=0 ----
    #pragma unroll
    for (int s = 0; s < 3; ++s) {
        cp_async16(swdst0 + s * (SLAB * 16), wsrc + (size_t)s * KTOT);
        cp_commit();
    }

    float xf[4][4];
    #pragma unroll
    for (int bb = 0; bb < 4; ++bb) {
        const float* xb = xp[bb];
        xf[bb][0] = __ldg(xb + c0);
        xf[bb][1] = __ldg(xb + c0 + 256);
        xf[bb][2] = __ldg(xb + c2);
        xf[bb][3] = __ldg(xb + c2 + 1);
    }

    #pragma unroll 4
    for (int ic = 0; ic < IC_; ++ic) {
        if (ic <= IC_ - 3)      cp_wait<2>();
        else if (ic == IC_ - 2) cp_wait<1>();
        else                    cp_wait<0>();
        __syncthreads();

        if (ic + 3 < IC_) {
            cp_async16(swdst0 + ((ic + 3) & (NBUF - 1)) * (SLAB * 16),
                       wsrc + (size_t)(ic + 3) * KTOT);
            cp_commit();
        }

        // pack current x
        unsigned long long xA[4], xB[4];
        #pragma unroll
        for (int bb = 0; bb < 4; ++bb) {
            xA[bb] = pack2(xf[bb][0], xf[bb][1]);
            xB[bb] = pack2(xf[bb][2], xf[bb][3]);
        }

        // prefetch x for ic+1 under this iteration's FMAs
        if (ic < IC_ - 1) {
            const int off = (ic + 1) * E_;
            #pragma unroll
            for (int bb = 0; bb < 4; ++bb) {
                const float* xb = xp[bb] + off;
                xf[bb][0] = __ldg(xb + c0);
                xf[bb][1] = __ldg(xb + c0 + 256);
                xf[bb][2] = __ldg(xb + c2);
                xf[bb][3] = __ldg(xb + c2 + 1);
            }
        }

        // compute: 8 o x 4 b x 2 fma2
        const float4* swrow = &sw[ic & (NBUF - 1)][lane];
        unsigned sa0 = (unsigned)__cvta_generic_to_shared(swrow);
        #pragma unroll
        for (int oo = 0; oo < 8; ++oo) {
            unsigned long long wA, wB;
            asm("ld.shared.v2.u64 {%0, %1}, [%2];"
                : "=l"(wA), "=l"(wB) : "r"(sa0 + oo * (KT * 16)));
            #pragma unroll
            for (int bb = 0; bb < 4; ++bb) {
                fma2(acc[oo][bb], wA, xA[bb]);
                fma2(acc[oo][bb], wB, xB[bb]);
            }
        }
    }

    // epilogue: lo+hi + bias, coalesced STG.32
    #pragma unroll
    for (int oo = 0; oo < 8; ++oo) {
        const int o = oh * 8 + oo;
        const float bo = __ldg(&bias[o]);
        #pragma unroll
        for (int bb = 0; bb < 4; ++bb) {
            float2 v = unpack2(acc[oo][bb]);
            out[(size_t)((bbase + bb) * OC_ + o) * KTOT + k] = v.x + v.y + bo;
        }
    }
}

extern "C" void kernel_launch(void* const* d_in, const int* in_sizes, int n_in,
                              void* d_out, int out_size)
{
    const float*  x    = (const float*)d_in[0];
    const float4* w4   = (const float4*)d_in[1];
    const float*  bias = (const float*)d_in[2];
    float*        out  = (float*)d_out;

    dim3 block(32, 8);
    dim3 grid((KTOT / KT) * 2);   // 4096 CTAs: (tile, oh-half)
    edges_kernel<<<grid, block>>>(x, w4, bias, out);
}

// round 7
// speedup vs baseline: 1.3477x; 1.0767x over previous
#include <cuda_runtime.h>
#include <cstdint>

#define B_    32
#define IC_   16
#define OC_   16
#define KTOT  65536      // (M-1)*(N-1)
#define E_    131584     // edges
#define VOFF  65792      // M*(N-1)
#define KT    32         // k per tile (never crosses a 256-wide row)
#define NBUF  4          // weight pipeline depth
#define NTILE (KTOT / KT)   // 2048

__device__ __forceinline__ unsigned long long pack2(float lo, float hi) {
    unsigned long long r;
    asm("mov.b64 %0, {%1, %2};" : "=l"(r) : "f"(lo), "f"(hi));
    return r;
}
__device__ __forceinline__ void fma2(unsigned long long &acc,
                                     unsigned long long a, unsigned long long b) {
    asm("fma.rn.f32x2 %0, %1, %2, %0;" : "+l"(acc) : "l"(a), "l"(b));
}
__device__ __forceinline__ float2 unpack2(unsigned long long v) {
    float2 f;
    asm("mov.b64 {%0, %1}, %2;" : "=f"(f.x), "=f"(f.y) : "l"(v));
    return f;
}
__device__ __forceinline__ void cp_async16(unsigned dst, const void* src) {
    asm volatile("cp.async.cg.shared.global [%0], [%1], 16;\n"
                 :: "r"(dst), "l"(src) : "memory");
}
__device__ __forceinline__ void cp_commit() {
    asm volatile("cp.async.commit_group;\n" ::: "memory");
}
template<int N>
__device__ __forceinline__ void cp_wait() {
    asm volatile("cp.async.wait_group %0;\n" :: "n"(N) : "memory");
}

// Persistent CTAs: 148 blocks of 512 threads, each walks ~14 k-tiles.
// Per tile: 32 k-lanes x 16 warps (y = oh*8 + bg), all 32 batches,
// all 16 o-channels => every weight element read from DRAM exactly once.
// The 4-deep cp.async weight pipeline runs CONTINUOUSLY across tiles.
__global__ __launch_bounds__(512, 1)
void edges_kernel(const float* __restrict__ x,
                  const float4* __restrict__ w4,
                  const float* __restrict__ bias,
                  float* __restrict__ out)
{
    __shared__ float4 sw[NBUF][16 * KT];   // [buf][o*32 + klocal]

    const int lane = threadIdx.x;
    const int y    = threadIdx.y;
    const int oh   = y >> 3;
    const int bg   = y & 7;
    const int bbase = bg * 4;
    const int gstride = gridDim.x;          // tiles stride

    // cooperative weight copy mapping (per-thread slot, add k0 + ic*KTOT)
    const int tld = y * 32 + lane;
    const float4* wbase = w4 + (size_t)((tld >> 5) * IC_) * KTOT + (tld & 31);
    unsigned swdst[NBUF];
    #pragma unroll
    for (int s = 0; s < NBUF; ++s)
        swdst[s] = (unsigned)__cvta_generic_to_shared(&sw[s][tld]);

    const float* xp[4];
    #pragma unroll
    for (int bb = 0; bb < 4; ++bb)
        xp[bb] = x + (size_t)((bbase + bb) * IC_) * E_;

    float bo[8];
    #pragma unroll
    for (int oo = 0; oo < 8; ++oo) bo[oo] = __ldg(&bias[oh * 8 + oo]);

    const int tile0  = blockIdx.x;
    const int ntiles = (NTILE - tile0 + gstride - 1) / gstride;
    const int mtot   = ntiles * IC_;

    // ---- stage-issue state (global stage counter; buffer = stage & 3) ----
    int s_ic = 0;
    const float4* s_w = wbase + tile0 * KT;     // base for issuing tile
    int issued = 0;
    #pragma unroll
    for (int s = 0; s < 3; ++s) {               // mtot >= 16*13, always ok
        cp_async16(swdst[s], s_w + (size_t)s_ic * KTOT);
        cp_commit();
        ++s_ic; ++issued;
    }

    // ---- x-gather state for current tile ----
    int k0 = tile0 * KT;
    int k  = k0 + lane;
    int c0 = k;
    int c2 = VOFF + (k0 >> 8) * 257 + (k0 & 255) + lane;

    float xf[4][4];
    #pragma unroll
    for (int bb = 0; bb < 4; ++bb) {
        const float* xb = xp[bb];
        xf[bb][0] = __ldg(xb + c0);
        xf[bb][1] = __ldg(xb + c0 + 256);
        xf[bb][2] = __ldg(xb + c2);
        xf[bb][3] = __ldg(xb + c2 + 1);
    }

    int m = 0;
    for (int t = 0; t < ntiles; ++t) {
        unsigned long long acc[8][4];
        #pragma unroll
        for (int oo = 0; oo < 8; ++oo)
            #pragma unroll
            for (int bb = 0; bb < 4; ++bb) acc[oo][bb] = 0ull;

        #pragma unroll 1
        for (int ic = 0; ic < IC_; ++ic, ++m) {
            // wait for stage m (keep up to 2 younger groups in flight)
            const int pend = issued - m - 1;
            if (pend >= 2)      cp_wait<2>();
            else if (pend == 1) cp_wait<1>();
            else                cp_wait<0>();
            __syncthreads();

            // issue stage m+3 (continuous across tile boundaries)
            if (issued < mtot) {
                cp_async16(swdst[issued & (NBUF - 1)], s_w + (size_t)s_ic * KTOT);
                cp_commit();
                if (++s_ic == IC_) { s_ic = 0; s_w += (size_t)gstride * KT; }
                ++issued;
            }

            // pack current x
            unsigned long long xA[4], xB[4];
            #pragma unroll
            for (int bb = 0; bb < 4; ++bb) {
                xA[bb] = pack2(xf[bb][0], xf[bb][1]);
                xB[bb] = pack2(xf[bb][2], xf[bb][3]);
            }

            // prefetch x for the NEXT stage (next ic, or next tile's ic=0)
            if (ic < IC_ - 1) {
                const int off = (ic + 1) * E_;
                #pragma unroll
                for (int bb = 0; bb < 4; ++bb) {
                    const float* xb = xp[bb] + off;
                    xf[bb][0] = __ldg(xb + c0);
                    xf[bb][1] = __ldg(xb + c0 + 256);
                    xf[bb][2] = __ldg(xb + c2);
                    xf[bb][3] = __ldg(xb + c2 + 1);
                }
            } else if (t + 1 < ntiles) {
                const int k0n = k0 + gstride * KT;
                const int c0n = k0n + lane;
                const int c2n = VOFF + (k0n >> 8) * 257 + (k0n & 255) + lane;
                #pragma unroll
                for (int bb = 0; bb < 4; ++bb) {
                    const float* xb = xp[bb];
                    xf[bb][0] = __ldg(xb + c0n);
                    xf[bb][1] = __ldg(xb + c0n + 256);
                    xf[bb][2] = __ldg(xb + c2n);
                    xf[bb][3] = __ldg(xb + c2n + 1);
                }
            }

            // compute: 8 o x 4 b x 2 fma2, explicit w double-buffer
            unsigned sa = (unsigned)__cvta_generic_to_shared(
                              &sw[m & (NBUF - 1)][(oh * 8) * KT + lane]);
            unsigned long long wA, wB, wA2, wB2;
            asm("ld.shared.v2.u64 {%0, %1}, [%2];" : "=l"(wA), "=l"(wB) : "r"(sa));
            #pragma unroll
            for (int oo = 0; oo < 8; ++oo) {
                if (oo < 7)
                    asm("ld.shared.v2.u64 {%0, %1}, [%2];"
                        : "=l"(wA2), "=l"(wB2) : "r"(sa + (oo + 1) * (KT * 16)));
                #pragma unroll
                for (int bb = 0; bb < 4; ++bb) {
                    fma2(acc[oo][bb], wA, xA[bb]);
                    fma2(acc[oo][bb], wB, xB[bb]);
                }
                wA = wA2; wB = wB2;
            }
        }

        // epilogue for this tile (overlaps the already-issued cp.async stages)
        #pragma unroll
        for (int oo = 0; oo < 8; ++oo) {
            const int o = oh * 8 + oo;
            #pragma unroll
            for (int bb = 0; bb < 4; ++bb) {
                float2 v = unpack2(acc[oo][bb]);
                out[(size_t)((bbase + bb) * OC_ + o) * KTOT + k] = v.x + v.y + bo[oo];
            }
        }

        // advance tile constants
        k0 += gstride * KT;
        k   = k0 + lane;
        c0  = k;
        c2  = VOFF + (k0 >> 8) * 257 + (k0 & 255) + lane;
    }
}

extern "C" void kernel_launch(void* const* d_in, const int* in_sizes, int n_in,
                              void* d_out, int out_size)
{
    const float*  x    = (const float*)d_in[0];
    const float4* w4   = (const float4*)d_in[1];
    const float*  bias = (const float*)d_in[2];
    float*        out  = (float*)d_out;

    dim3 block(32, 16);
    dim3 grid(148);   // persistent: one CTA per SM
    edges_kernel<<<grid, block>>>(x, w4, bias, out);
}